// round 6
// baseline (speedup 1.0000x reference)
#include <cuda_runtime.h>
#include <float.h>

#define THRESHOLD 0.5f
#define B 256
#define HW 49            // 7*7
#define C_INTERM 1000
#define C_VGG 512
#define N4 (B * HW * C_VGG / 4)   // 1,605,632 float4
#define VEC 8                      // float4 per thread in k2

// Thresholded CAM value per (batch, spatial) cell. 12544 floats.
__device__ float g_tvals[B * HW];

// ---------------------------------------------------------------------------
// k1: per-batch argmax over branchA[b,0:1000] (first-index-wins) via float4
//     loads + warp shuffle reduction, then gather interm[b,hw,idx],
//     threshold, write g_tvals. One 256-thread block per batch.
// ---------------------------------------------------------------------------
__global__ __launch_bounds__(256) void argmax_gather_kernel(
    const float* __restrict__ branchA,   // [B, 1000]
    const float* __restrict__ interm)    // [B, 49, 1000]
{
    const int b    = blockIdx.x;
    const int tid  = threadIdx.x;
    const int lane = tid & 31;
    const int wid  = tid >> 5;

    const float4* row4 = (const float4*)(branchA + (size_t)b * C_INTERM);

    float best_v = -FLT_MAX;
    int   best_i = C_INTERM;
    if (tid < 250) {                      // 250 float4 = 1000 floats
        float4 x = __ldg(row4 + tid);
        const int i0 = tid * 4;
        // in-order compares preserve first-index-wins within the quad
        if (x.x > best_v) { best_v = x.x; best_i = i0; }
        if (x.y > best_v) { best_v = x.y; best_i = i0 + 1; }
        if (x.z > best_v) { best_v = x.z; best_i = i0 + 2; }
        if (x.w > best_v) { best_v = x.w; best_i = i0 + 3; }
    }

    // Warp butterfly on (v, i): lexicographic max (v desc, i asc).
    #pragma unroll
    for (int off = 16; off > 0; off >>= 1) {
        float ov = __shfl_xor_sync(0xFFFFFFFFu, best_v, off);
        int   oi = __shfl_xor_sync(0xFFFFFFFFu, best_i, off);
        if (ov > best_v || (ov == best_v && oi < best_i)) { best_v = ov; best_i = oi; }
    }

    __shared__ float s_wv[8];
    __shared__ int   s_wi[8];
    __shared__ int   s_idx;

    if (lane == 0) { s_wv[wid] = best_v; s_wi[wid] = best_i; }
    __syncthreads();

    if (wid == 0) {
        float fv = (lane < 8) ? s_wv[lane] : -FLT_MAX;
        int   fi = (lane < 8) ? s_wi[lane] : C_INTERM;
        #pragma unroll
        for (int off = 4; off > 0; off >>= 1) {
            float ov = __shfl_xor_sync(0xFFFFFFFFu, fv, off);
            int   oi = __shfl_xor_sync(0xFFFFFFFFu, fi, off);
            if (ov > fv || (ov == fv && oi < fi)) { fv = ov; fi = oi; }
        }
        if (lane == 0) s_idx = fi;
    }
    __syncthreads();

    const int idx = s_idx;

    if (tid < HW) {
        float a = __ldg(interm + ((size_t)b * HW + tid) * C_INTERM + idx);
        g_tvals[b * HW + tid] = (a > THRESHOLD) ? a : 0.0f;
    }
}

// ---------------------------------------------------------------------------
// k2: streaming subtract. Launched with programmatic stream serialization:
//     starts concurrently with k1, front-issues all vgg loads (independent
//     of k1), then waits on the grid dependency before consuming g_tvals.
// ---------------------------------------------------------------------------
__global__ __launch_bounds__(256) void subtract_kernel(
    const float4* __restrict__ vgg,   // [N4]
    float4* __restrict__ out)
{
    const int base = blockIdx.x * (256 * VEC) + threadIdx.x;

    // Independent prelude: 8 LDG.128 in flight while k1 still runs.
    float4 v[VEC];
    #pragma unroll
    for (int k = 0; k < VEC; k++)
        v[k] = vgg[base + k * 256];

    // Wait for k1 completion (g_tvals ready).
    cudaGridDependencySynchronize();

    #pragma unroll
    for (int k = 0; k < VEC; k++) {
        const int i = base + k * 256;
        const float t = g_tvals[i >> 7];      // 128 float4 per (b,hw) cell
        float4 r = v[k];
        r.x -= t; r.y -= t; r.z -= t; r.w -= t;
        out[i] = r;
    }
}

extern "C" void kernel_launch(void* const* d_in, const int* in_sizes, int n_in,
                              void* d_out, int out_size) {
    const float* vgg_end = (const float*)d_in[0];  // [256,7,7,512]
    const float* interm  = (const float*)d_in[1];  // [256,7,7,1000]
    const float* branchA = (const float*)d_in[2];  // [256,1000]
    float*       out     = (float*)d_out;

    // k1: normal launch.
    argmax_gather_kernel<<<B, 256>>>(branchA, interm);

    // k2: programmatic dependent launch — overlaps with k1.
    cudaLaunchConfig_t cfg = {};
    cfg.gridDim  = dim3(N4 / (256 * VEC), 1, 1);   // 784 blocks, exact
    cfg.blockDim = dim3(256, 1, 1);
    cfg.dynamicSmemBytes = 0;
    cfg.stream = 0;   // legacy default stream (the capturing stream)

    cudaLaunchAttribute attr;
    attr.id = cudaLaunchAttributeProgrammaticStreamSerialization;
    attr.val.programmaticStreamSerializationAllowed = 1;
    cfg.attrs    = &attr;
    cfg.numAttrs = 1;

    cudaLaunchKernelEx(&cfg, subtract_kernel, (const float4*)vgg_end, (float4*)out);
}

// round 7
// speedup vs baseline: 1.1557x; 1.1557x over previous
#include <cuda_runtime.h>
#include <float.h>

#define THRESHOLD 0.5f
#define B 256
#define HW 49            // 7*7
#define C_INTERM 1000
#define C_VGG 512
#define F4_PER_BATCH (HW * C_VGG / 4)       // 6272
#define PARTS 4
#define F4_PER_PART (F4_PER_BATCH / PARTS)  // 1568 = 6*256 + 32

// 16-byte cp.async, L2-only caching (.cg), no register file involvement.
__device__ __forceinline__ void cp_async16(void* smem_dst, const void* gmem_src) {
    unsigned s = (unsigned)__cvta_generic_to_shared(smem_dst);
    asm volatile("cp.async.cg.shared.global [%0], [%1], 16;\n"
                 :: "r"(s), "l"(gmem_src) : "memory");
}
__device__ __forceinline__ void cp_async_commit() {
    asm volatile("cp.async.commit_group;\n" ::: "memory");
}
__device__ __forceinline__ void cp_async_wait_all() {
    asm volatile("cp.async.wait_group 0;\n" ::: "memory");
}

// ---------------------------------------------------------------------------
// Fused kernel, 4 blocks per batch:
//   Phase 0: cp.async the ENTIRE quarter-batch (25KB) into smem (no regs)
//   Phase A: argmax over branchA[b,:] (first-index-wins), gather CAM -> s_t
//   Phase B: smem -> subtract -> streaming store
// ---------------------------------------------------------------------------
__global__ __launch_bounds__(256) void fused_kernel(
    const float*  __restrict__ branchA,  // [B, 1000]
    const float*  __restrict__ interm,   // [B, 49, 1000]
    const float4* __restrict__ vgg,      // [B*49*512/4]
    float4*       __restrict__ out)
{
    __shared__ float4 s_buf[F4_PER_PART];   // 25,088 B
    __shared__ float  s_t[HW];
    __shared__ float  s_wv[8];
    __shared__ int    s_wi[8];

    const int b    = blockIdx.x >> 2;
    const int part = blockIdx.x & 3;
    const int tid  = threadIdx.x;
    const int lane = tid & 31;
    const int wid  = tid >> 5;

    const int loc0  = part * F4_PER_PART + tid;   // local f4 index in batch
    const int base4 = b * F4_PER_BATCH + loc0;    // global f4 index

    // ---------------- Phase 0: async-copy full quarter into smem -----------
    #pragma unroll
    for (int k = 0; k < 6; k++)
        cp_async16(&s_buf[tid + k * 256], &vgg[base4 + k * 256]);
    if (tid < 32)
        cp_async16(&s_buf[tid + 6 * 256], &vgg[base4 + 6 * 256]);
    cp_async_commit();

    // ---------------- Phase A: argmax (first-index-wins) -------------------
    const float4* row4 = (const float4*)(branchA + (size_t)b * C_INTERM);

    float best_v = -FLT_MAX;
    int   best_i = C_INTERM;
    if (tid < 250) {                       // 250 float4 = 1000 floats
        float4 x = __ldg(row4 + tid);
        const int i0 = tid * 4;
        if (x.x > best_v) { best_v = x.x; best_i = i0; }
        if (x.y > best_v) { best_v = x.y; best_i = i0 + 1; }
        if (x.z > best_v) { best_v = x.z; best_i = i0 + 2; }
        if (x.w > best_v) { best_v = x.w; best_i = i0 + 3; }
    }

    #pragma unroll
    for (int off = 16; off > 0; off >>= 1) {
        float ov = __shfl_xor_sync(0xFFFFFFFFu, best_v, off);
        int   oi = __shfl_xor_sync(0xFFFFFFFFu, best_i, off);
        if (ov > best_v || (ov == best_v && oi < best_i)) { best_v = ov; best_i = oi; }
    }

    if (lane == 0) { s_wv[wid] = best_v; s_wi[wid] = best_i; }
    __syncthreads();

    // Every thread reduces the 8 partials serially (broadcast smem reads) —
    // avoids a second shuffle stage + barrier.
    int idx;
    {
        float fv = s_wv[0]; int fi = s_wi[0];
        #pragma unroll
        for (int k = 1; k < 8; k++) {
            float ov = s_wv[k]; int oi = s_wi[k];
            if (ov > fv || (ov == fv && oi < fi)) { fv = ov; fi = oi; }
        }
        idx = fi;
    }

    // Gather + threshold the 49 CAM values (one dependent DRAM roundtrip).
    if (tid < HW) {
        float a = __ldg(interm + ((size_t)b * HW + tid) * C_INTERM + idx);
        s_t[tid] = (a > THRESHOLD) ? a : 0.0f;
    }

    // Same-thread cp.async data: wait_group 0 suffices for s_buf;
    // the barrier publishes s_t.
    cp_async_wait_all();
    __syncthreads();

    // ---------------- Phase B: smem -> subtract -> store --------------------
    #pragma unroll
    for (int k = 0; k < 6; k++) {
        const float tv = s_t[(loc0 + k * 256) >> 7];   // 128 f4 per cell
        float4 r = s_buf[tid + k * 256];
        r.x -= tv; r.y -= tv; r.z -= tv; r.w -= tv;
        __stcs(&out[base4 + k * 256], r);
    }
    if (tid < 32) {
        const float tv = s_t[(loc0 + 6 * 256) >> 7];
        float4 r = s_buf[tid + 6 * 256];
        r.x -= tv; r.y -= tv; r.z -= tv; r.w -= tv;
        __stcs(&out[base4 + 6 * 256], r);
    }
}

extern "C" void kernel_launch(void* const* d_in, const int* in_sizes, int n_in,
                              void* d_out, int out_size) {
    const float* vgg_end = (const float*)d_in[0];  // [256,7,7,512]
    const float* interm  = (const float*)d_in[1];  // [256,7,7,1000]
    const float* branchA = (const float*)d_in[2];  // [256,1000]
    float*       out     = (float*)d_out;

    fused_kernel<<<B * PARTS, 256>>>(branchA, interm,
                                     (const float4*)vgg_end, (float4*)out);
}